// round 1
// baseline (speedup 1.0000x reference)
#include <cuda_runtime.h>
#include <math.h>

#define B       32
#define EMB     512
#define CTXD    512
#define HID     1024
#define K2      2048
#define V       32000
#define TSTEPS  64
#define START_TOK 1

// ---------------- persistent device scratch (no allocations allowed) ----------------
__device__ float g_h0[2][B*HID];
__device__ float g_c0[B*HID];
__device__ float g_h1[2][B*HID];
__device__ float g_c1[B*HID];
__device__ float g_logits[B*V];
__device__ int   g_tok[B];

// ---------------- packed f32x2 helpers (sm_100+ dual-FMA pipe) ----------------
static __device__ __forceinline__ unsigned long long ffma2(unsigned long long a,
                                                           unsigned long long b,
                                                           unsigned long long c){
    unsigned long long d;
    asm("fma.rn.f32x2 %0, %1, %2, %3;" : "=l"(d) : "l"(a), "l"(b), "l"(c));
    return d;
}
static __device__ __forceinline__ unsigned long long pack2(float x, float y){
    unsigned long long d;
    asm("mov.b64 %0, {%1, %2};" : "=l"(d) : "f"(x), "f"(y));
    return d;
}
static __device__ __forceinline__ float2 unpack2(unsigned long long a){
    float2 r;
    asm("mov.b64 {%0, %1}, %2;" : "=f"(r.x), "=f"(r.y) : "l"(a));
    return r;
}
static __device__ __forceinline__ float sigmoidf_(float x){ return 1.0f/(1.0f + expf(-x)); }

// ---------------- init: zero states, seed tokens ----------------
__global__ void init_kernel(){
    int i = blockIdx.x*blockDim.x + threadIdx.x;
    if (i < B*HID){ g_h0[0][i]=0.f; g_c0[i]=0.f; g_h1[0][i]=0.f; g_c1[i]=0.f; }
    if (i < B) g_tok[i] = START_TOK;
}

// ---------------- fused LSTM cell: GEMM(K=2048) + gates + state update ----------------
// Block handles 8 hidden units (= 32 gate rows) x all 32 batches. Grid = 128.
// X (per batch, K=2048) = LAYER0: [emb[tok] | ctx | h0_prev]   LAYER1: [h0_cur | h1_prev]
// W rows: gate g, unit j -> row g*HID+j of [Wih | Whh] concat over K.
template<int LAYER>
__global__ void __launch_bounds__(256) lstm_cell_kernel(
    const float* __restrict__ Wih, const float* __restrict__ Whh,
    const float* __restrict__ bih, const float* __restrict__ bhh,
    const float* __restrict__ emb, const float* __restrict__ ctx,
    int rp)
{
    __shared__ float Xs[64][33];   // [k-tile][batch], padded (conflict-free scalar reads)
    __shared__ float Ws[32][64];   // [gate-row][k-tile] (broadcast reads)
    __shared__ float sbuf[32][33]; // gate exchange
    __shared__ int   stok[B];

    const int tid  = threadIdx.x;
    const int lane = tid & 31;     // = batch
    const int w    = tid >> 5;     // warp 0..7, owns 4 gate-rows
    const int u0   = blockIdx.x * 8;
    const int wp   = rp ^ 1;

    if (LAYER == 0 && tid < B) stok[tid] = g_tok[tid];
    __syncthreads();

    unsigned long long acc[4] = {0ull,0ull,0ull,0ull};

    for (int k0 = 0; k0 < K2; k0 += 64){
        // ---- load X tile (transposed into [k][b]) ----
        #pragma unroll
        for (int j = 0; j < 2; j++){
            int id = tid + j*256;
            int b  = id >> 4;
            int kq = (id & 15) << 2;
            int kg = k0 + kq;
            const float* src;
            if (LAYER == 0){
                if (kg < 512)       src = emb + stok[b]*EMB + kg;
                else if (kg < 1024) src = ctx + b*CTXD + (kg - 512);
                else                src = &g_h0[rp][b*HID + (kg - 1024)];
            } else {
                if (kg < 1024)      src = &g_h0[rp ^ 1][b*HID + kg];      // h0 current
                else                src = &g_h1[rp][b*HID + (kg - 1024)]; // h1 prev
            }
            float4 v = *(const float4*)src;
            Xs[kq+0][b]=v.x; Xs[kq+1][b]=v.y; Xs[kq+2][b]=v.z; Xs[kq+3][b]=v.w;
        }
        // ---- load W tile ----
        #pragma unroll
        for (int j = 0; j < 2; j++){
            int id = tid + j*256;
            int lr = id >> 4;                          // local row 0..31
            int kq = (id & 15) << 2;
            int wr = (lr >> 3)*HID + u0 + (lr & 7);    // gate*HID + unit
            const float* src = (k0 < 1024) ? (Wih + (size_t)wr*HID + (k0 + kq))
                                           : (Whh + (size_t)wr*HID + (k0 - 1024 + kq));
            *(float4*)&Ws[lr][kq] = *(const float4*)src;
        }
        __syncthreads();
        // ---- f32x2 inner product ----
        #pragma unroll
        for (int kk = 0; kk < 64; kk += 4){
            unsigned long long x01 = pack2(Xs[kk  ][lane], Xs[kk+1][lane]);
            unsigned long long x23 = pack2(Xs[kk+2][lane], Xs[kk+3][lane]);
            #pragma unroll
            for (int i = 0; i < 4; i++){
                ulonglong2 wv = *(const ulonglong2*)&Ws[w*4 + i][kk];
                acc[i] = ffma2(wv.x, x01, acc[i]);
                acc[i] = ffma2(wv.y, x23, acc[i]);
            }
        }
        __syncthreads();
    }

    // ---- exchange gate partials ----
    #pragma unroll
    for (int i = 0; i < 4; i++){
        float2 p = unpack2(acc[i]);
        sbuf[w*4 + i][lane] = p.x + p.y;
    }
    __syncthreads();

    // ---- 256 threads = 32 batch x 8 units: activations + state update ----
    {
        int b = tid & 31;
        int u = tid >> 5;
        int j = u0 + u;
        float gi = sbuf[u      ][b] + bih[j]         + bhh[j];
        float gf = sbuf[8 + u  ][b] + bih[HID + j]   + bhh[HID + j];
        float gg = sbuf[16 + u ][b] + bih[2*HID + j] + bhh[2*HID + j];
        float go = sbuf[24 + u ][b] + bih[3*HID + j] + bhh[3*HID + j];
        float iv = sigmoidf_(gi), fv = sigmoidf_(gf), ov = sigmoidf_(go);
        float tv = tanhf(gg);
        float* cp = (LAYER == 0) ? g_c0 : g_c1;
        float* hp = (LAYER == 0) ? g_h0[wp] : g_h1[wp];
        int idx = b*HID + j;
        float cn = fv * cp[idx] + iv * tv;
        cp[idx] = cn;
        hp[idx] = ov * tanhf(cn);
    }
}

// ---------------- logits GEMM: 32 x 32000, K=1024 ----------------
// Block tile: 128 vocab x 32 batch, micro 4v x 4b, f32x2 packed over batch pairs.
__global__ void __launch_bounds__(256) logits_kernel(
    const float* __restrict__ Wlin, const float* __restrict__ blin, int hp)
{
    __shared__ float Xs[32][36];    // [k][batch]
    __shared__ float Ws[32][132];   // [k][vocab-local]
    const int tid = threadIdx.x;
    const int bq  = tid & 7;        // batch quad index (b0 = bq*4)
    const int vg  = tid >> 3;       // vocab group 0..31 (v = v0 + vg*4 + i)
    const int v0  = blockIdx.x * 128;
    const float* __restrict__ h1 = g_h1[hp];

    unsigned long long acc[4][2];
    #pragma unroll
    for (int i = 0; i < 4; i++){ acc[i][0] = 0ull; acc[i][1] = 0ull; }

    for (int k0 = 0; k0 < HID; k0 += 32){
        #pragma unroll
        for (int j = 0; j < 4; j++){
            int idx = tid + j*256;
            int b  = idx >> 5;
            int kk = idx & 31;
            Xs[kk][b] = h1[b*HID + k0 + kk];
        }
        #pragma unroll
        for (int j = 0; j < 16; j++){
            int idx = tid + j*256;
            int v  = idx >> 5;
            int kk = idx & 31;
            Ws[kk][v] = Wlin[(size_t)(v0 + v)*HID + k0 + kk];
        }
        __syncthreads();
        #pragma unroll
        for (int kk = 0; kk < 32; kk++){
            ulonglong2 xv = *(const ulonglong2*)&Xs[kk][bq*4];  // {b0,b1},{b2,b3}
            float4 wv = *(const float4*)&Ws[kk][vg*4];
            unsigned long long w0 = pack2(wv.x, wv.x);
            unsigned long long w1 = pack2(wv.y, wv.y);
            unsigned long long w2 = pack2(wv.z, wv.z);
            unsigned long long w3 = pack2(wv.w, wv.w);
            acc[0][0] = ffma2(w0, xv.x, acc[0][0]); acc[0][1] = ffma2(w0, xv.y, acc[0][1]);
            acc[1][0] = ffma2(w1, xv.x, acc[1][0]); acc[1][1] = ffma2(w1, xv.y, acc[1][1]);
            acc[2][0] = ffma2(w2, xv.x, acc[2][0]); acc[2][1] = ffma2(w2, xv.y, acc[2][1]);
            acc[3][0] = ffma2(w3, xv.x, acc[3][0]); acc[3][1] = ffma2(w3, xv.y, acc[3][1]);
        }
        __syncthreads();
    }
    #pragma unroll
    for (int i = 0; i < 4; i++){
        int v = v0 + vg*4 + i;
        float bb = blin[v];
        float2 p0 = unpack2(acc[i][0]);
        float2 p1 = unpack2(acc[i][1]);
        int b0 = bq*4;
        g_logits[(b0+0)*V + v] = p0.x + bb;
        g_logits[(b0+1)*V + v] = p0.y + bb;
        g_logits[(b0+2)*V + v] = p1.x + bb;
        g_logits[(b0+3)*V + v] = p1.y + bb;
    }
}

// ---------------- softmax + argmax (first-index tiebreak, matching jnp.argmax) ----------------
__global__ void __launch_bounds__(1024) softmax_kernel(float* __restrict__ out, int t)
{
    __shared__ float sval[1024];
    __shared__ int   sidx[1024];
    const int b   = blockIdx.x;
    const int tid = threadIdx.x;
    const float* __restrict__ row = g_logits + b*V;

    float m = -INFINITY; int mi = V;
    for (int v = tid; v < V; v += 1024){
        float x = row[v];
        if (x > m){ m = x; mi = v; }
    }
    sval[tid] = m; sidx[tid] = mi;
    __syncthreads();
    for (int s = 512; s > 0; s >>= 1){
        if (tid < s){
            float xo = sval[tid+s]; int io = sidx[tid+s];
            if (xo > sval[tid] || (xo == sval[tid] && io < sidx[tid])){
                sval[tid] = xo; sidx[tid] = io;
            }
        }
        __syncthreads();
    }
    const float gmax = sval[0];
    if (tid == 0) g_tok[b] = sidx[0];
    __syncthreads();

    float ssum = 0.f;
    for (int v = tid; v < V; v += 1024) ssum += expf(row[v] - gmax);
    sval[tid] = ssum;
    __syncthreads();
    for (int s = 512; s > 0; s >>= 1){
        if (tid < s) sval[tid] += sval[tid + s];
        __syncthreads();
    }
    const float inv = 1.0f / sval[0];
    float* __restrict__ dst = out + ((size_t)b*TSTEPS + t)*V;
    for (int v = tid; v < V; v += 1024) dst[v] = expf(row[v] - gmax) * inv;
}

// ---------------- launch ----------------
extern "C" void kernel_launch(void* const* d_in, const int* in_sizes, int n_in,
                              void* d_out, int out_size)
{
    // input order: context, [max_len], emb, W_ih0, W_hh0, b_ih0, b_hh0,
    //              W_ih1, W_hh1, b_ih1, b_hh1, W_lin, b_lin
    int s = (n_in >= 13) ? 1 : ((in_sizes[1] == 1) ? 1 : 0);
    const float* ctx  = (const float*)d_in[0];
    const float* emb  = (const float*)d_in[1+s];
    const float* Wih0 = (const float*)d_in[2+s];
    const float* Whh0 = (const float*)d_in[3+s];
    const float* bih0 = (const float*)d_in[4+s];
    const float* bhh0 = (const float*)d_in[5+s];
    const float* Wih1 = (const float*)d_in[6+s];
    const float* Whh1 = (const float*)d_in[7+s];
    const float* bih1 = (const float*)d_in[8+s];
    const float* bhh1 = (const float*)d_in[9+s];
    const float* Wlin = (const float*)d_in[10+s];
    const float* blin = (const float*)d_in[11+s];
    float* out = (float*)d_out;

    init_kernel<<<(B*HID + 255)/256, 256>>>();
    for (int t = 0; t < TSTEPS; t++){
        int rp = t & 1;  // read parity for h buffers
        lstm_cell_kernel<0><<<HID/8, 256>>>(Wih0, Whh0, bih0, bhh0, emb, ctx, rp);
        lstm_cell_kernel<1><<<HID/8, 256>>>(Wih1, Whh1, bih1, bhh1, emb, ctx, rp);
        logits_kernel<<<V/128, 256>>>(Wlin, blin, rp ^ 1);
        softmax_kernel<<<B, 1024>>>(out, t);
    }
}

// round 2
// speedup vs baseline: 1.4547x; 1.4547x over previous
#include <cuda_runtime.h>
#include <math.h>

#define B       32
#define EMB     512
#define CTXD    512
#define HID     1024
#define K2      2048
#define V       32000
#define TSTEPS  64
#define START_TOK 1

// ---------------- persistent device scratch (no allocations allowed) ----------------
__device__ float g_h0[2][B*HID];
__device__ float g_c0[B*HID];
__device__ float g_h1[2][B*HID];
__device__ float g_c1[B*HID];
__device__ float g_logits[B*V];
__device__ int   g_tok[B];

// ---------------- packed f32x2 helpers (sm_100+ dual-FMA pipe) ----------------
static __device__ __forceinline__ unsigned long long ffma2(unsigned long long a,
                                                           unsigned long long b,
                                                           unsigned long long c){
    unsigned long long d;
    asm("fma.rn.f32x2 %0, %1, %2, %3;" : "=l"(d) : "l"(a), "l"(b), "l"(c));
    return d;
}
static __device__ __forceinline__ unsigned long long pack2(float x, float y){
    unsigned long long d;
    asm("mov.b64 %0, {%1, %2};" : "=l"(d) : "f"(x), "f"(y));
    return d;
}
static __device__ __forceinline__ float2 unpack2(unsigned long long a){
    float2 r;
    asm("mov.b64 {%0, %1}, %2;" : "=f"(r.x), "=f"(r.y) : "l"(a));
    return r;
}
static __device__ __forceinline__ float sigmoidf_(float x){ return 1.0f/(1.0f + expf(-x)); }

// ---------------- init: zero states, seed tokens ----------------
__global__ void init_kernel(){
    int i = blockIdx.x*blockDim.x + threadIdx.x;
    if (i < B*HID){ g_h0[0][i]=0.f; g_c0[i]=0.f; g_h1[0][i]=0.f; g_c1[i]=0.f; }
    if (i < B) g_tok[i] = START_TOK;
}

// ---------------- fused LSTM cell: GEMM(K=2048) + gates + state update ----------------
// Block handles 8 hidden units (= 32 gate rows) x all 32 batches. Grid = 128.
// X (per batch, K=2048) = LAYER0: [emb[tok] | ctx | h0_prev]   LAYER1: [h0_cur | h1_prev]
// W rows: gate g, unit j -> row g*HID+j of [Wih | Whh] concat over K.
template<int LAYER>
__global__ void __launch_bounds__(256) lstm_cell_kernel(
    const float* __restrict__ Wih, const float* __restrict__ Whh,
    const float* __restrict__ bih, const float* __restrict__ bhh,
    const float* __restrict__ emb, const float* __restrict__ ctx,
    int rp)
{
    __shared__ float Xs[64][33];   // [k-tile][batch], padded (conflict-free scalar reads)
    __shared__ float Ws[32][64];   // [gate-row][k-tile] (broadcast reads)
    __shared__ float sbuf[32][33]; // gate exchange
    __shared__ int   stok[B];

    const int tid  = threadIdx.x;
    const int lane = tid & 31;     // = batch
    const int w    = tid >> 5;     // warp 0..7, owns 4 gate-rows
    const int u0   = blockIdx.x * 8;
    const int wp   = rp ^ 1;

    if (LAYER == 0 && tid < B) stok[tid] = g_tok[tid];
    __syncthreads();

    unsigned long long acc[4] = {0ull,0ull,0ull,0ull};

    for (int k0 = 0; k0 < K2; k0 += 64){
        // ---- load X tile (transposed into [k][b]) ----
        #pragma unroll
        for (int j = 0; j < 2; j++){
            int id = tid + j*256;
            int b  = id >> 4;
            int kq = (id & 15) << 2;
            int kg = k0 + kq;
            const float* src;
            if (LAYER == 0){
                if (kg < 512)       src = emb + stok[b]*EMB + kg;
                else if (kg < 1024) src = ctx + b*CTXD + (kg - 512);
                else                src = &g_h0[rp][b*HID + (kg - 1024)];
            } else {
                if (kg < 1024)      src = &g_h0[rp ^ 1][b*HID + kg];      // h0 current
                else                src = &g_h1[rp][b*HID + (kg - 1024)]; // h1 prev
            }
            float4 v = *(const float4*)src;
            Xs[kq+0][b]=v.x; Xs[kq+1][b]=v.y; Xs[kq+2][b]=v.z; Xs[kq+3][b]=v.w;
        }
        // ---- load W tile ----
        #pragma unroll
        for (int j = 0; j < 2; j++){
            int id = tid + j*256;
            int lr = id >> 4;                          // local row 0..31
            int kq = (id & 15) << 2;
            int wr = (lr >> 3)*HID + u0 + (lr & 7);    // gate*HID + unit
            const float* src = (k0 < 1024) ? (Wih + (size_t)wr*HID + (k0 + kq))
                                           : (Whh + (size_t)wr*HID + (k0 - 1024 + kq));
            *(float4*)&Ws[lr][kq] = *(const float4*)src;
        }
        __syncthreads();
        // ---- f32x2 inner product ----
        #pragma unroll
        for (int kk = 0; kk < 64; kk += 4){
            unsigned long long x01 = pack2(Xs[kk  ][lane], Xs[kk+1][lane]);
            unsigned long long x23 = pack2(Xs[kk+2][lane], Xs[kk+3][lane]);
            #pragma unroll
            for (int i = 0; i < 4; i++){
                ulonglong2 wv = *(const ulonglong2*)&Ws[w*4 + i][kk];
                acc[i] = ffma2(wv.x, x01, acc[i]);
                acc[i] = ffma2(wv.y, x23, acc[i]);
            }
        }
        __syncthreads();
    }

    // ---- exchange gate partials ----
    #pragma unroll
    for (int i = 0; i < 4; i++){
        float2 p = unpack2(acc[i]);
        sbuf[w*4 + i][lane] = p.x + p.y;
    }
    __syncthreads();

    // ---- 256 threads = 32 batch x 8 units: activations + state update ----
    {
        int b = tid & 31;
        int u = tid >> 5;
        int j = u0 + u;
        float gi = sbuf[u      ][b] + bih[j]         + bhh[j];
        float gf = sbuf[8 + u  ][b] + bih[HID + j]   + bhh[HID + j];
        float gg = sbuf[16 + u ][b] + bih[2*HID + j] + bhh[2*HID + j];
        float go = sbuf[24 + u ][b] + bih[3*HID + j] + bhh[3*HID + j];
        float iv = sigmoidf_(gi), fv = sigmoidf_(gf), ov = sigmoidf_(go);
        float tv = tanhf(gg);
        float* cp = (LAYER == 0) ? g_c0 : g_c1;
        float* hp = (LAYER == 0) ? g_h0[wp] : g_h1[wp];
        int idx = b*HID + j;
        float cn = fv * cp[idx] + iv * tv;
        cp[idx] = cn;
        hp[idx] = ov * tanhf(cn);
    }
}

// ---------------- logits GEMM: 32 x 32000, K=1024 ----------------
// Block tile: 128 vocab x 32 batch, micro 4v x 4b, f32x2 packed over batch pairs.
__global__ void __launch_bounds__(256) logits_kernel(
    const float* __restrict__ Wlin, const float* __restrict__ blin, int hp)
{
    __shared__ float Xs[32][36];    // [k][batch]
    __shared__ float Ws[32][132];   // [k][vocab-local]
    const int tid = threadIdx.x;
    const int bq  = tid & 7;        // batch quad index (b0 = bq*4)
    const int vg  = tid >> 3;       // vocab group 0..31 (v = v0 + vg*4 + i)
    const int v0  = blockIdx.x * 128;
    const float* __restrict__ h1 = g_h1[hp];

    unsigned long long acc[4][2];
    #pragma unroll
    for (int i = 0; i < 4; i++){ acc[i][0] = 0ull; acc[i][1] = 0ull; }

    for (int k0 = 0; k0 < HID; k0 += 32){
        #pragma unroll
        for (int j = 0; j < 4; j++){
            int idx = tid + j*256;
            int b  = idx >> 5;
            int kk = idx & 31;
            Xs[kk][b] = h1[b*HID + k0 + kk];
        }
        #pragma unroll
        for (int j = 0; j < 16; j++){
            int idx = tid + j*256;
            int v  = idx >> 5;
            int kk = idx & 31;
            Ws[kk][v] = Wlin[(size_t)(v0 + v)*HID + k0 + kk];
        }
        __syncthreads();
        #pragma unroll
        for (int kk = 0; kk < 32; kk++){
            ulonglong2 xv = *(const ulonglong2*)&Xs[kk][bq*4];  // {b0,b1},{b2,b3}
            float4 wv = *(const float4*)&Ws[kk][vg*4];
            unsigned long long w0 = pack2(wv.x, wv.x);
            unsigned long long w1 = pack2(wv.y, wv.y);
            unsigned long long w2 = pack2(wv.z, wv.z);
            unsigned long long w3 = pack2(wv.w, wv.w);
            acc[0][0] = ffma2(w0, xv.x, acc[0][0]); acc[0][1] = ffma2(w0, xv.y, acc[0][1]);
            acc[1][0] = ffma2(w1, xv.x, acc[1][0]); acc[1][1] = ffma2(w1, xv.y, acc[1][1]);
            acc[2][0] = ffma2(w2, xv.x, acc[2][0]); acc[2][1] = ffma2(w2, xv.y, acc[2][1]);
            acc[3][0] = ffma2(w3, xv.x, acc[3][0]); acc[3][1] = ffma2(w3, xv.y, acc[3][1]);
        }
        __syncthreads();
    }
    #pragma unroll
    for (int i = 0; i < 4; i++){
        int v = v0 + vg*4 + i;
        float bb = blin[v];
        float2 p0 = unpack2(acc[i][0]);
        float2 p1 = unpack2(acc[i][1]);
        int b0 = bq*4;
        g_logits[(b0+0)*V + v] = p0.x + bb;
        g_logits[(b0+1)*V + v] = p0.y + bb;
        g_logits[(b0+2)*V + v] = p1.x + bb;
        g_logits[(b0+3)*V + v] = p1.y + bb;
    }
}

// ---------------- softmax + argmax (first-index tiebreak, matching jnp.argmax) ----------------
__global__ void __launch_bounds__(1024) softmax_kernel(float* __restrict__ out, int t)
{
    __shared__ float sval[1024];
    __shared__ int   sidx[1024];
    const int b   = blockIdx.x;
    const int tid = threadIdx.x;
    const float* __restrict__ row = g_logits + b*V;

    float m = -INFINITY; int mi = V;
    for (int v = tid; v < V; v += 1024){
        float x = row[v];
        if (x > m){ m = x; mi = v; }
    }
    sval[tid] = m; sidx[tid] = mi;
    __syncthreads();
    for (int s = 512; s > 0; s >>= 1){
        if (tid < s){
            float xo = sval[tid+s]; int io = sidx[tid+s];
            if (xo > sval[tid] || (xo == sval[tid] && io < sidx[tid])){
                sval[tid] = xo; sidx[tid] = io;
            }
        }
        __syncthreads();
    }
    const float gmax = sval[0];
    if (tid == 0) g_tok[b] = sidx[0];
    __syncthreads();

    float ssum = 0.f;
    for (int v = tid; v < V; v += 1024) ssum += expf(row[v] - gmax);
    sval[tid] = ssum;
    __syncthreads();
    for (int s = 512; s > 0; s >>= 1){
        if (tid < s) sval[tid] += sval[tid + s];
        __syncthreads();
    }
    const float inv = 1.0f / sval[0];
    float* __restrict__ dst = out + ((size_t)b*TSTEPS + t)*V;
    for (int v = tid; v < V; v += 1024) dst[v] = expf(row[v] - gmax) * inv;
}

// ---------------- launch ----------------
extern "C" void kernel_launch(void* const* d_in, const int* in_sizes, int n_in,
                              void* d_out, int out_size)
{
    // input order: context, [max_len], emb, W_ih0, W_hh0, b_ih0, b_hh0,
    //              W_ih1, W_hh1, b_ih1, b_hh1, W_lin, b_lin
    int s = (n_in >= 13) ? 1 : ((in_sizes[1] == 1) ? 1 : 0);
    const float* ctx  = (const float*)d_in[0];
    const float* emb  = (const float*)d_in[1+s];
    const float* Wih0 = (const float*)d_in[2+s];
    const float* Whh0 = (const float*)d_in[3+s];
    const float* bih0 = (const float*)d_in[4+s];
    const float* bhh0 = (const float*)d_in[5+s];
    const float* Wih1 = (const float*)d_in[6+s];
    const float* Whh1 = (const float*)d_in[7+s];
    const float* bih1 = (const float*)d_in[8+s];
    const float* bhh1 = (const float*)d_in[9+s];
    const float* Wlin = (const float*)d_in[10+s];
    const float* blin = (const float*)d_in[11+s];
    float* out = (float*)d_out;

    init_kernel<<<(B*HID + 255)/256, 256>>>();
    for (int t = 0; t < TSTEPS; t++){
        int rp = t & 1;  // read parity for h buffers
        lstm_cell_kernel<0><<<HID/8, 256>>>(Wih0, Whh0, bih0, bhh0, emb, ctx, rp);
        lstm_cell_kernel<1><<<HID/8, 256>>>(Wih1, Whh1, bih1, bhh1, emb, ctx, rp);
        logits_kernel<<<V/128, 256>>>(Wlin, blin, rp ^ 1);
        softmax_kernel<<<B, 1024>>>(out, t);
    }
}

// round 3
// speedup vs baseline: 1.6353x; 1.1242x over previous
#include <cuda_runtime.h>
#include <math.h>

#define B       32
#define HID     1024
#define K2      2048
#define V       32000
#define TSTEPS  64
#define NROWS   4096
#define KSPLIT  8
#define KCHUNK  256
#define START_TOK 1

// ---------------- persistent device scratch ----------------
__device__ float g_WtL[(size_t)HID*V];      // W_lin^T [k][v]
__device__ float g_Wt0[(size_t)K2*NROWS];   // layer0 [Wih|Whh]^T [k][row]
__device__ float g_Wt1[(size_t)K2*NROWS];
__device__ float g_h0[B*HID], g_c0[B*HID], g_h1[B*HID], g_c1[B*HID];
__device__ float g_part[(size_t)KSPLIT*NROWS*B];
__device__ float g_logits[(size_t)B*V];
__device__ int   g_tok[B];
__device__ float g_pm[B*8], g_ps[B*8];
__device__ int   g_pi[B*8];

// ---------------- f32x2 helpers ----------------
static __device__ __forceinline__ unsigned long long ffma2(unsigned long long a,
                                                           unsigned long long b,
                                                           unsigned long long c){
    unsigned long long d;
    asm("fma.rn.f32x2 %0, %1, %2, %3;" : "=l"(d) : "l"(a), "l"(b), "l"(c));
    return d;
}
static __device__ __forceinline__ unsigned long long pack2(float x, float y){
    unsigned long long d;
    asm("mov.b64 %0, {%1, %2};" : "=l"(d) : "f"(x), "f"(y));
    return d;
}
static __device__ __forceinline__ float2 unpack2(unsigned long long a){
    float2 r;
    asm("mov.b64 {%0, %1}, %2;" : "=f"(r.x), "=f"(r.y) : "l"(a));
    return r;
}
static __device__ __forceinline__ float sigmoidf_(float x){ return 1.0f/(1.0f + expf(-x)); }

// ---------------- init ----------------
__global__ void init_kernel(){
    int i = blockIdx.x*blockDim.x + threadIdx.x;
    if (i < B*HID){ g_h0[i]=0.f; g_c0[i]=0.f; g_h1[i]=0.f; g_c1[i]=0.f; }
    if (i < B) g_tok[i] = START_TOK;
}

// ---------------- weight transposes (deterministic, every replay) ----------------
__global__ void tr_lin(const float* __restrict__ W){
    __shared__ float t[32][33];
    int vb = blockIdx.x*32, kb = blockIdx.y*32;
    int x = threadIdx.x, y = threadIdx.y;
    #pragma unroll
    for (int j = 0; j < 32; j += 8) t[y+j][x] = W[(size_t)(vb+y+j)*HID + kb + x];
    __syncthreads();
    #pragma unroll
    for (int j = 0; j < 32; j += 8) g_WtL[(size_t)(kb+y+j)*V + vb + x] = t[x][y+j];
}

template<int L>
__global__ void tr_lstm(const float* __restrict__ Wih, const float* __restrict__ Whh){
    __shared__ float t[32][33];
    int rb = blockIdx.x*32, kb = blockIdx.y*32;
    int x = threadIdx.x, y = threadIdx.y;
    const float* src = (kb < 1024) ? Wih : Whh;
    int ko = (kb < 1024) ? kb : kb - 1024;
    #pragma unroll
    for (int j = 0; j < 32; j += 8) t[y+j][x] = src[(size_t)(rb+y+j)*HID + ko + x];
    __syncthreads();
    float* dst = L ? g_Wt1 : g_Wt0;
    #pragma unroll
    for (int j = 0; j < 32; j += 8) dst[(size_t)(kb+y+j)*NROWS + rb + x] = t[x][y+j];
}

// ---------------- LSTM GEMM partials: rows 4096 x batch 32, K split 8 ----------------
// 256 blocks x 128 thr. Thread = one gate-row (coalesced W^T LDG), 32 batches
// in 16 f32x2 accumulators. X chunk [256 k][32 b] in smem (broadcast LDS.128).
template<int L>
__global__ void __launch_bounds__(128) lstm_gemm(const float* __restrict__ emb,
                                                 const float* __restrict__ ctx)
{
    __shared__ __align__(16) float Xs[KCHUNK][32];
    const int tid   = threadIdx.x;
    const int split = blockIdx.x & 7;
    const int row   = (blockIdx.x >> 3)*128 + tid;
    const int kbase = split*KCHUNK;
    const float* __restrict__ Wt = L ? g_Wt1 : g_Wt0;

    // ---- stage X chunk: thread -> batch b, quarter q ----
    {
        int b = tid >> 2, q = tid & 3;
        const float* src;
        if (L == 0){
            if (split < 2)      src = emb + (size_t)g_tok[b]*512 + kbase;
            else if (split < 4) src = ctx + (size_t)b*512 + (kbase - 512);
            else                src = g_h0 + b*HID + (kbase - 1024);
        } else {
            if (split < 4)      src = g_h0 + b*HID + kbase;
            else                src = g_h1 + b*HID + (kbase - 1024);
        }
        #pragma unroll
        for (int i = 0; i < 16; i++){
            int kf = (q + i*4)*4;
            float4 v = *(const float4*)(src + kf);
            Xs[kf+0][b]=v.x; Xs[kf+1][b]=v.y; Xs[kf+2][b]=v.z; Xs[kf+3][b]=v.w;
        }
    }
    __syncthreads();

    unsigned long long acc[16];
    #pragma unroll
    for (int i = 0; i < 16; i++) acc[i] = 0ull;

    const float* __restrict__ wp = Wt + (size_t)kbase*NROWS + row;
    float wA[16], wB[16];
    #pragma unroll
    for (int i = 0; i < 16; i++) wA[i] = wp[(size_t)i*NROWS];

    #pragma unroll 1
    for (int kb = 0; kb < KCHUNK; kb += 32){
        #pragma unroll
        for (int i = 0; i < 16; i++) wB[i] = wp[(size_t)(kb+16+i)*NROWS];
        #pragma unroll
        for (int i = 0; i < 16; i++){
            unsigned long long ww = pack2(wA[i], wA[i]);
            const ulonglong2* xr = (const ulonglong2*)Xs[kb+i];
            #pragma unroll
            for (int j = 0; j < 8; j++){
                ulonglong2 x2 = xr[j];
                acc[2*j]   = ffma2(ww, x2.x, acc[2*j]);
                acc[2*j+1] = ffma2(ww, x2.y, acc[2*j+1]);
            }
        }
        if (kb + 32 < KCHUNK){
            #pragma unroll
            for (int i = 0; i < 16; i++) wA[i] = wp[(size_t)(kb+32+i)*NROWS];
        }
        #pragma unroll
        for (int i = 0; i < 16; i++){
            unsigned long long ww = pack2(wB[i], wB[i]);
            const ulonglong2* xr = (const ulonglong2*)Xs[kb+16+i];
            #pragma unroll
            for (int j = 0; j < 8; j++){
                ulonglong2 x2 = xr[j];
                acc[2*j]   = ffma2(ww, x2.x, acc[2*j]);
                acc[2*j+1] = ffma2(ww, x2.y, acc[2*j+1]);
            }
        }
    }

    float* pp = g_part + ((size_t)split*NROWS + row)*32;
    #pragma unroll
    for (int j = 0; j < 8; j++){
        float2 a = unpack2(acc[2*j]);
        float2 c = unpack2(acc[2*j+1]);
        *(float4*)(pp + j*4) = make_float4(a.x, a.y, c.x, c.y);
    }
}

// ---------------- reduce partials + gates + state update ----------------
template<int L>
__global__ void __launch_bounds__(256) lstm_gates(const float* __restrict__ bih,
                                                  const float* __restrict__ bhh)
{
    int idx = blockIdx.x*256 + threadIdx.x;  // 0..32767
    int b = idx & 31, u = idx >> 5;
    float g[4];
    #pragma unroll
    for (int gg = 0; gg < 4; gg++){
        int r = gg*HID + u;
        float s = bih[r] + bhh[r];
        #pragma unroll
        for (int sp = 0; sp < KSPLIT; sp++)
            s += g_part[((size_t)sp*NROWS + r)*32 + b];
        g[gg] = s;
    }
    float iv = sigmoidf_(g[0]), fv = sigmoidf_(g[1]), ov = sigmoidf_(g[3]);
    float tv = tanhf(g[2]);
    float* cp = L ? g_c1 : g_c0;
    float* hp = L ? g_h1 : g_h0;
    int id = b*HID + u;
    float cn = fv*cp[id] + iv*tv;
    cp[id] = cn;
    hp[id] = ov*tanhf(cn);
}

// ---------------- logits GEMM: 32000 rows x 32 batch, K=1024 ----------------
// 250 blocks x 128 thr. Thread = one vocab row; h1 staged in 4 chunks of 256 k.
__global__ void __launch_bounds__(128) logits_kernel(const float* __restrict__ blin)
{
    __shared__ __align__(16) float Xs[KCHUNK][32];
    const int tid = threadIdx.x;
    const int v   = blockIdx.x*128 + tid;

    unsigned long long acc[16];
    #pragma unroll
    for (int i = 0; i < 16; i++) acc[i] = 0ull;

    for (int cc = 0; cc < 4; cc++){
        const int kbase = cc*KCHUNK;
        __syncthreads();
        {
            int b = tid >> 2, q = tid & 3;
            const float* src = g_h1 + b*HID + kbase;
            #pragma unroll
            for (int i = 0; i < 16; i++){
                int kf = (q + i*4)*4;
                float4 x = *(const float4*)(src + kf);
                Xs[kf+0][b]=x.x; Xs[kf+1][b]=x.y; Xs[kf+2][b]=x.z; Xs[kf+3][b]=x.w;
            }
        }
        __syncthreads();

        const float* __restrict__ wp = g_WtL + (size_t)kbase*V + v;
        float wA[16], wB[16];
        #pragma unroll
        for (int i = 0; i < 16; i++) wA[i] = wp[(size_t)i*V];

        #pragma unroll 1
        for (int kb = 0; kb < KCHUNK; kb += 32){
            #pragma unroll
            for (int i = 0; i < 16; i++) wB[i] = wp[(size_t)(kb+16+i)*V];
            #pragma unroll
            for (int i = 0; i < 16; i++){
                unsigned long long ww = pack2(wA[i], wA[i]);
                const ulonglong2* xr = (const ulonglong2*)Xs[kb+i];
                #pragma unroll
                for (int j = 0; j < 8; j++){
                    ulonglong2 x2 = xr[j];
                    acc[2*j]   = ffma2(ww, x2.x, acc[2*j]);
                    acc[2*j+1] = ffma2(ww, x2.y, acc[2*j+1]);
                }
            }
            if (kb + 32 < KCHUNK){
                #pragma unroll
                for (int i = 0; i < 16; i++) wA[i] = wp[(size_t)(kb+32+i)*V];
            }
            #pragma unroll
            for (int i = 0; i < 16; i++){
                unsigned long long ww = pack2(wB[i], wB[i]);
                const ulonglong2* xr = (const ulonglong2*)Xs[kb+16+i];
                #pragma unroll
                for (int j = 0; j < 8; j++){
                    ulonglong2 x2 = xr[j];
                    acc[2*j]   = ffma2(ww, x2.x, acc[2*j]);
                    acc[2*j+1] = ffma2(ww, x2.y, acc[2*j+1]);
                }
            }
        }
    }

    float bb = blin[v];
    #pragma unroll
    for (int j = 0; j < 8; j++){
        float2 a = unpack2(acc[2*j]);
        float2 c = unpack2(acc[2*j+1]);
        g_logits[(size_t)(4*j+0)*V + v] = a.x + bb;
        g_logits[(size_t)(4*j+1)*V + v] = a.y + bb;
        g_logits[(size_t)(4*j+2)*V + v] = c.x + bb;
        g_logits[(size_t)(4*j+3)*V + v] = c.y + bb;
    }
}

// ---------------- softmax in 3 parallel passes (8 chunks x 32 batch) ----------------
#define CHUNK (V/8)   // 4000

__global__ void __launch_bounds__(256) smax1(){
    __shared__ float sv[256]; __shared__ int si[256];
    int c = blockIdx.x, b = blockIdx.y, tid = threadIdx.x;
    const float* row = g_logits + (size_t)b*V + c*CHUNK;
    float m = -INFINITY; int mi = 1<<30;
    for (int v = tid; v < CHUNK; v += 256){
        float x = row[v];
        if (x > m){ m = x; mi = v; }
    }
    sv[tid] = m; si[tid] = mi;
    __syncthreads();
    for (int s = 128; s > 0; s >>= 1){
        if (tid < s){
            float xo = sv[tid+s]; int io = si[tid+s];
            if (xo > sv[tid] || (xo == sv[tid] && io < si[tid])){ sv[tid]=xo; si[tid]=io; }
        }
        __syncthreads();
    }
    if (tid == 0){ g_pm[b*8+c] = sv[0]; g_pi[b*8+c] = si[0] + c*CHUNK; }
}

__global__ void __launch_bounds__(256) smax2(){
    __shared__ float sv[256];
    int c = blockIdx.x, b = blockIdx.y, tid = threadIdx.x;
    float gm = g_pm[b*8];
    #pragma unroll
    for (int i = 1; i < 8; i++) gm = fmaxf(gm, g_pm[b*8+i]);
    const float* row = g_logits + (size_t)b*V + c*CHUNK;
    float s = 0.f;
    for (int v = tid; v < CHUNK; v += 256) s += expf(row[v] - gm);
    sv[tid] = s;
    __syncthreads();
    for (int r = 128; r > 0; r >>= 1){
        if (tid < r) sv[tid] += sv[tid+r];
        __syncthreads();
    }
    if (tid == 0){
        g_ps[b*8+c] = sv[0];
        if (c == 0){
            int bi = 1<<30;
            for (int i = 0; i < 8; i++)
                if (g_pm[b*8+i] == gm && g_pi[b*8+i] < bi) bi = g_pi[b*8+i];
            g_tok[b] = bi;
        }
    }
}

__global__ void __launch_bounds__(256) smax3(float* __restrict__ out, int t){
    int c = blockIdx.x, b = blockIdx.y, tid = threadIdx.x;
    float gm = g_pm[b*8];
    #pragma unroll
    for (int i = 1; i < 8; i++) gm = fmaxf(gm, g_pm[b*8+i]);
    float sum = 0.f;
    #pragma unroll
    for (int i = 0; i < 8; i++) sum += g_ps[b*8+i];
    float inv = 1.0f / sum;
    const float* row = g_logits + (size_t)b*V + c*CHUNK;
    float* dst = out + ((size_t)b*TSTEPS + t)*V + c*CHUNK;
    for (int v = tid; v < CHUNK; v += 256) dst[v] = expf(row[v] - gm) * inv;
}

// ---------------- launch ----------------
extern "C" void kernel_launch(void* const* d_in, const int* in_sizes, int n_in,
                              void* d_out, int out_size)
{
    int s = (n_in >= 13) ? 1 : ((in_sizes[1] == 1) ? 1 : 0);
    const float* ctx  = (const float*)d_in[0];
    const float* emb  = (const float*)d_in[1+s];
    const float* Wih0 = (const float*)d_in[2+s];
    const float* Whh0 = (const float*)d_in[3+s];
    const float* bih0 = (const float*)d_in[4+s];
    const float* bhh0 = (const float*)d_in[5+s];
    const float* Wih1 = (const float*)d_in[6+s];
    const float* Whh1 = (const float*)d_in[7+s];
    const float* bih1 = (const float*)d_in[8+s];
    const float* bhh1 = (const float*)d_in[9+s];
    const float* Wlin = (const float*)d_in[10+s];
    const float* blin = (const float*)d_in[11+s];
    float* out = (float*)d_out;

    init_kernel<<<128, 256>>>();
    tr_lin<<<dim3(V/32, HID/32), dim3(32,8)>>>(Wlin);
    tr_lstm<0><<<dim3(NROWS/32, K2/32), dim3(32,8)>>>(Wih0, Whh0);
    tr_lstm<1><<<dim3(NROWS/32, K2/32), dim3(32,8)>>>(Wih1, Whh1);

    for (int t = 0; t < TSTEPS; t++){
        lstm_gemm<0><<<256, 128>>>(emb, ctx);
        lstm_gates<0><<<128, 256>>>(bih0, bhh0);
        lstm_gemm<1><<<256, 128>>>(emb, ctx);
        lstm_gates<1><<<128, 256>>>(bih1, bhh1);
        logits_kernel<<<250, 128>>>(blin);
        smax1<<<dim3(8,B), 256>>>();
        smax2<<<dim3(8,B), 256>>>();
        smax3<<<dim3(8,B), 256>>>(out, t);
    }
}

// round 7
// speedup vs baseline: 2.4985x; 1.5278x over previous
#include <cuda_runtime.h>
#include <cuda_bf16.h>
#include <math.h>

#define B       32
#define HID     1024
#define K2      2048
#define V       32000
#define TSTEPS  64
#define NROWS   4096
#define KSPLIT  8
#define KCHUNK  256
#define START_TOK 1

// ================= persistent device scratch =================
__device__ float g_Wt0[(size_t)K2*NROWS];   // layer0 [Wih|Whh]^T [k][row]  (fp32)
__device__ float g_Wt1[(size_t)K2*NROWS];
__device__ uint4 g_WL[(size_t)V*256];       // W_lin 2-split bf16 interleaved
__device__ uint4 g_XL[32*256];              // h1 2-split bf16
__device__ float g_h0[B*HID], g_c0[B*HID], g_h1[B*HID], g_c1[B*HID];
__device__ float g_part[(size_t)KSPLIT*NROWS*B];
__device__ float g_logits[(size_t)B*V];
__device__ int   g_tok[B];
__device__ float g_pm[B*8], g_ps[B*8];

// ================= f32x2 helpers (fp32 LSTM path) =================
static __device__ __forceinline__ unsigned long long ffma2(unsigned long long a,
                                                           unsigned long long b,
                                                           unsigned long long c){
    unsigned long long d;
    asm("fma.rn.f32x2 %0, %1, %2, %3;" : "=l"(d) : "l"(a), "l"(b), "l"(c));
    return d;
}
static __device__ __forceinline__ unsigned long long pack2(float x, float y){
    unsigned long long d;
    asm("mov.b64 %0, {%1, %2};" : "=l"(d) : "f"(x), "f"(y));
    return d;
}
static __device__ __forceinline__ float2 unpack2(unsigned long long a){
    float2 r;
    asm("mov.b64 {%0, %1}, %2;" : "=f"(r.x), "=f"(r.y) : "l"(a));
    return r;
}
static __device__ __forceinline__ float sigmoidf_(float x){ return 1.0f/(1.0f + expf(-x)); }

// ================= bf16 helpers (logits path) =================
static __device__ __forceinline__ unsigned short f2bf(float x){
    __nv_bfloat16 h = __float2bfloat16(x);
    return *reinterpret_cast<unsigned short*>(&h);
}
static __device__ __forceinline__ float bf2f(unsigned short u){
    __nv_bfloat16 h = *reinterpret_cast<__nv_bfloat16*>(&u);
    return __bfloat162float(h);
}
static __device__ __forceinline__ uint4 pack4(float4 v){  // 2-way split, interleaved per 4k
    unsigned short hx=f2bf(v.x), hy=f2bf(v.y), hz=f2bf(v.z), hw=f2bf(v.w);
    unsigned short lx=f2bf(v.x-bf2f(hx)), ly=f2bf(v.y-bf2f(hy));
    unsigned short lz=f2bf(v.z-bf2f(hz)), lw=f2bf(v.w-bf2f(hw));
    uint4 o;
    o.x = (unsigned)hx | ((unsigned)hy<<16);
    o.y = (unsigned)lx | ((unsigned)ly<<16);
    o.z = (unsigned)hz | ((unsigned)hw<<16);
    o.w = (unsigned)lz | ((unsigned)lw<<16);
    return o;
}
static __device__ __forceinline__ void store_hl(unsigned short* rowbase, int k, float v){
    unsigned short hi = f2bf(v);
    unsigned short lo = f2bf(v - bf2f(hi));
    int idx = (k>>2)*8 + ((k>>1)&1)*4 + (k&1);
    rowbase[idx]   = hi;
    rowbase[idx+2] = lo;
}
static __device__ __forceinline__ void cpa16(void* dst, const void* src){
    unsigned ds = (unsigned)__cvta_generic_to_shared(dst);
    asm volatile("cp.async.cg.shared.global [%0], [%1], 16;\n" :: "r"(ds), "l"(src));
}
#define CP_COMMIT asm volatile("cp.async.commit_group;\n")
#define CP_WAIT(n) asm volatile("cp.async.wait_group %0;\n" :: "n"(n))
static __device__ __forceinline__ uint2 ld2(const char* base, int row, int pair){
    return *(const uint2*)(base + row*544 + pair*8);
}
static __device__ __forceinline__ void mma16816(float* d,
    unsigned a0, unsigned a1, unsigned a2, unsigned a3, unsigned b0, unsigned b1){
    asm volatile("mma.sync.aligned.m16n8k16.row.col.f32.bf16.bf16.f32 "
        "{%0,%1,%2,%3},{%4,%5,%6,%7},{%8,%9},{%0,%1,%2,%3};"
        : "+f"(d[0]), "+f"(d[1]), "+f"(d[2]), "+f"(d[3])
        : "r"(a0), "r"(a1), "r"(a2), "r"(a3), "r"(b0), "r"(b1));
}

// ================= init =================
__global__ void init_kernel(){
    int i = blockIdx.x*blockDim.x + threadIdx.x;
    if (i < B*HID){ g_h0[i]=0.f; g_c0[i]=0.f; g_h1[i]=0.f; g_c1[i]=0.f; }
    if (i < 8192) ((uint4*)g_XL)[i] = make_uint4(0,0,0,0);
    if (i < B) g_tok[i] = START_TOK;
}

// ================= prep: LSTM weight transpose (fp32), logits weight split (bf16) =================
template<int L>
__global__ void tr_lstm(const float* __restrict__ Wih, const float* __restrict__ Whh){
    __shared__ float t[32][33];
    int rb = blockIdx.x*32, kb = blockIdx.y*32;
    int x = threadIdx.x, y = threadIdx.y;
    const float* src = (kb < 1024) ? Wih : Whh;
    int ko = (kb < 1024) ? kb : kb - 1024;
    #pragma unroll
    for (int j = 0; j < 32; j += 8) t[y+j][x] = src[(size_t)(rb+y+j)*1024 + ko + x];
    __syncthreads();
    float* dst = L ? g_Wt1 : g_Wt0;
    #pragma unroll
    for (int j = 0; j < 32; j += 8) dst[(size_t)(kb+y+j)*NROWS + rb + x] = t[x][y+j];
}
__global__ void prep_lin(const float* __restrict__ W){
    int v = blockIdx.x, j = threadIdx.x;
    float4 x = *(const float4*)(W + (size_t)v*1024 + j*4);
    g_WL[(size_t)v*256 + j] = pack4(x);
}

// ================= LSTM GEMM partials (fp32, R3-proven): rows 4096 x batch 32, K split 8 =================
template<int L>
__global__ void __launch_bounds__(128) lstm_gemm(const float* __restrict__ emb,
                                                 const float* __restrict__ ctx)
{
    __shared__ __align__(16) float Xs[KCHUNK][32];
    const int tid   = threadIdx.x;
    const int split = blockIdx.x & 7;
    const int row   = (blockIdx.x >> 3)*128 + tid;
    const int kbase = split*KCHUNK;
    const float* __restrict__ Wt = L ? g_Wt1 : g_Wt0;

    {
        int b = tid >> 2, q = tid & 3;
        const float* src;
        if (L == 0){
            if (split < 2)      src = emb + (size_t)g_tok[b]*512 + kbase;
            else if (split < 4) src = ctx + (size_t)b*512 + (kbase - 512);
            else                src = g_h0 + b*HID + (kbase - 1024);
        } else {
            if (split < 4)      src = g_h0 + b*HID + kbase;
            else                src = g_h1 + b*HID + (kbase - 1024);
        }
        #pragma unroll
        for (int i = 0; i < 16; i++){
            int kf = (q + i*4)*4;
            float4 v = *(const float4*)(src + kf);
            Xs[kf+0][b]=v.x; Xs[kf+1][b]=v.y; Xs[kf+2][b]=v.z; Xs[kf+3][b]=v.w;
        }
    }
    __syncthreads();

    unsigned long long acc[16];
    #pragma unroll
    for (int i = 0; i < 16; i++) acc[i] = 0ull;

    const float* __restrict__ wp = Wt + (size_t)kbase*NROWS + row;
    float wA[16], wB[16];
    #pragma unroll
    for (int i = 0; i < 16; i++) wA[i] = wp[(size_t)i*NROWS];

    #pragma unroll 1
    for (int kb = 0; kb < KCHUNK; kb += 32){
        #pragma unroll
        for (int i = 0; i < 16; i++) wB[i] = wp[(size_t)(kb+16+i)*NROWS];
        #pragma unroll
        for (int i = 0; i < 16; i++){
            unsigned long long ww = pack2(wA[i], wA[i]);
            const ulonglong2* xr = (const ulonglong2*)Xs[kb+i];
            #pragma unroll
            for (int j = 0; j < 8; j++){
                ulonglong2 x2 = xr[j];
                acc[2*j]   = ffma2(ww, x2.x, acc[2*j]);
                acc[2*j+1] = ffma2(ww, x2.y, acc[2*j+1]);
            }
        }
        if (kb + 32 < KCHUNK){
            #pragma unroll
            for (int i = 0; i < 16; i++) wA[i] = wp[(size_t)(kb+32+i)*NROWS];
        }
        #pragma unroll
        for (int i = 0; i < 16; i++){
            unsigned long long ww = pack2(wB[i], wB[i]);
            const ulonglong2* xr = (const ulonglong2*)Xs[kb+16+i];
            #pragma unroll
            for (int j = 0; j < 8; j++){
                ulonglong2 x2 = xr[j];
                acc[2*j]   = ffma2(ww, x2.x, acc[2*j]);
                acc[2*j+1] = ffma2(ww, x2.y, acc[2*j+1]);
            }
        }
    }

    float* pp = g_part + ((size_t)split*NROWS + row)*32;
    #pragma unroll
    for (int j = 0; j < 8; j++){
        float2 a = unpack2(acc[2*j]);
        float2 c = unpack2(acc[2*j+1]);
        *(float4*)(pp + j*4) = make_float4(a.x, a.y, c.x, c.y);
    }
}

// ================= reduce partials + gates + state update (fp32) =================
template<int L>
__global__ void __launch_bounds__(256) lstm_gates(const float* __restrict__ bih,
                                                  const float* __restrict__ bhh)
{
    int idx = blockIdx.x*256 + threadIdx.x;  // 0..32767
    int b = idx & 31, u = idx >> 5;
    float g[4];
    #pragma unroll
    for (int gg = 0; gg < 4; gg++){
        int r = gg*HID + u;
        float s = bih[r] + bhh[r];
        #pragma unroll
        for (int sp = 0; sp < KSPLIT; sp++)
            s += g_part[((size_t)sp*NROWS + r)*32 + b];
        g[gg] = s;
    }
    float iv = sigmoidf_(g[0]), fv = sigmoidf_(g[1]), ov = sigmoidf_(g[3]);
    float tv = tanhf(g[2]);
    float* cp = L ? g_c1 : g_c0;
    float* hp = L ? g_h1 : g_h0;
    int id = b*HID + u;
    float cn = fv*cp[id] + iv*tv;
    cp[id] = cn;
    float h = ov*tanhf(cn);
    hp[id] = h;
    if (L == 1) store_hl((unsigned short*)g_XL + b*2048, u, h);
}

// ================= logits: 3-term 2-split bf16 MMA (32000x32, K=1024) =================
__global__ void __launch_bounds__(256) logits_mma(const float* __restrict__ blin)
{
    extern __shared__ __align__(16) char sm[];
    const int tid = threadIdx.x, lane = tid & 31, w = tid >> 5;
    const int mi = w & 3, ki = w >> 2;
    const uint4* __restrict__ Wsrc = g_WL + (size_t)blockIdx.x*64*256;
    const uint4* __restrict__ Xsrc = g_XL;

    float d[4][4];
    #pragma unroll
    for (int i = 0; i < 4; i++){ d[i][0]=0.f; d[i][1]=0.f; d[i][2]=0.f; d[i][3]=0.f; }

    {
        char* smw = sm; char* smx = sm + 34816;
        #pragma unroll
        for (int j = 0; j < 8; j++){
            int s = tid + j*256, row = s >> 5, c = s & 31;
            cpa16(smw + row*544 + c*16, Wsrc + (size_t)row*256 + c);
        }
        #pragma unroll
        for (int j = 0; j < 4; j++){
            int s = tid + j*256, row = s >> 5, c = s & 31;
            cpa16(smx + row*544 + c*16, Xsrc + (size_t)row*256 + c);
        }
        CP_COMMIT;
    }

    for (int ck = 0; ck < 8; ck++){
        if (ck < 7){
            char* smw = sm + ((ck+1)&1)*52224; char* smx = smw + 34816;
            #pragma unroll
            for (int j = 0; j < 8; j++){
                int s = tid + j*256, row = s >> 5, c = s & 31;
                cpa16(smw + row*544 + c*16, Wsrc + (size_t)row*256 + (ck+1)*32 + c);
            }
            #pragma unroll
            for (int j = 0; j < 4; j++){
                int s = tid + j*256, row = s >> 5, c = s & 31;
                cpa16(smx + row*544 + c*16, Xsrc + (size_t)row*256 + (ck+1)*32 + c);
            }
            CP_COMMIT;
            CP_WAIT(1);
        } else {
            CP_WAIT(0);
        }
        __syncthreads();
        const char* smw = sm + (ck&1)*52224;
        const char* smx = smw + 34816;
        const int r0 = mi*16 + (lane>>2);
        #pragma unroll
        for (int s = 0; s < 4; s++){
            int ap = (ki*4 + s)*8 + (lane&3);
            uint2 A0 = ld2(smw, r0,   ap);
            uint2 A1 = ld2(smw, r0+8, ap);
            uint2 A2 = ld2(smw, r0,   ap+4);
            uint2 A3 = ld2(smw, r0+8, ap+4);
            #pragma unroll
            for (int nt = 0; nt < 4; nt++){
                int n = nt*8 + (lane>>2);
                uint2 B0 = ld2(smx, n, ap);
                uint2 B1 = ld2(smx, n, ap+4);
                mma16816(d[nt], A0.x,A1.x,A2.x,A3.x, B0.x,B1.x);   // hi*hi
                mma16816(d[nt], A0.x,A1.x,A2.x,A3.x, B0.y,B1.y);   // hi*lo
                mma16816(d[nt], A0.y,A1.y,A2.y,A3.y, B0.x,B1.x);   // lo*hi
            }
        }
        __syncthreads();
    }

    float* Gs = (float*)sm;   // [2][64][33]
    {
        int r = mi*16 + (lane>>2), cb = (lane&3)*2;
        #pragma unroll
        for (int nt = 0; nt < 4; nt++){
            int n = nt*8 + cb;
            Gs[(ki*64 + r  )*33 + n  ] = d[nt][0];
            Gs[(ki*64 + r  )*33 + n+1] = d[nt][1];
            Gs[(ki*64 + r+8)*33 + n  ] = d[nt][2];
            Gs[(ki*64 + r+8)*33 + n+1] = d[nt][3];
        }
    }
    __syncthreads();
    #pragma unroll
    for (int j = 0; j < 8; j++){
        int idx = tid + j*256;
        int b = idx >> 6, r = idx & 63;
        int v = blockIdx.x*64 + r;
        g_logits[(size_t)b*V + v] = Gs[r*33 + b] + Gs[(64 + r)*33 + b] + blin[v];
    }
}

// ================= softmax + exact fp32 argmax (eps-margin) =================
#define CHUNK (V/8)   // 4000

__global__ void __launch_bounds__(256) smax1(){
    __shared__ float sv[256];
    int c = blockIdx.x, b = blockIdx.y, tid = threadIdx.x;
    const float* row = g_logits + (size_t)b*V + c*CHUNK;
    float m = -INFINITY;
    for (int v = tid; v < CHUNK; v += 256) m = fmaxf(m, row[v]);
    sv[tid] = m;
    __syncthreads();
    for (int s = 128; s > 0; s >>= 1){
        if (tid < s) sv[tid] = fmaxf(sv[tid], sv[tid+s]);
        __syncthreads();
    }
    if (tid == 0) g_pm[b*8+c] = sv[0];
}

__global__ void __launch_bounds__(256) argmax_exact(const float* __restrict__ Wlin,
                                                    const float* __restrict__ blin){
    __shared__ int   cand[64];
    __shared__ float cval[64];
    __shared__ int   ncand;
    int b = blockIdx.x, tid = threadIdx.x;
    if (tid == 0) ncand = 0;
    __syncthreads();
    float gm = g_pm[b*8];
    #pragma unroll
    for (int i = 1; i < 8; i++) gm = fmaxf(gm, g_pm[b*8+i]);
    const float thr = gm - 1e-3f;
    const float* row = g_logits + (size_t)b*V;
    for (int v = tid; v < V; v += 256){
        if (row[v] >= thr){
            int sl = atomicAdd(&ncand, 1);
            if (sl < 64) cand[sl] = v;
        }
    }
    __syncthreads();
    int nc = min(ncand, 64);
    int w = tid >> 5, lane = tid & 31;
    const float* h = g_h1 + b*HID;
    for (int ci = w; ci < nc; ci += 8){
        int v = cand[ci];
        const float* wr = Wlin + (size_t)v*1024;
        float s = 0.f;
        #pragma unroll 8
        for (int k = lane; k < 1024; k += 32) s += h[k]*wr[k];
        #pragma unroll
        for (int o = 16; o > 0; o >>= 1) s += __shfl_xor_sync(0xffffffffu, s, o);
        if (lane == 0) cval[ci] = s + blin[v];
    }
    __syncthreads();
    if (tid == 0){
        float bm = -INFINITY; int bi = 1<<30;
        for (int i = 0; i < nc; i++){
            if (cval[i] > bm || (cval[i] == bm && cand[i] < bi)){ bm = cval[i]; bi = cand[i]; }
        }
        g_tok[b] = bi;
    }
}

__global__ void __launch_bounds__(256) smax2(){
    __shared__ float sv[256];
    int c = blockIdx.x, b = blockIdx.y, tid = threadIdx.x;
    float gm = g_pm[b*8];
    #pragma unroll
    for (int i = 1; i < 8; i++) gm = fmaxf(gm, g_pm[b*8+i]);
    const float* row = g_logits + (size_t)b*V + c*CHUNK;
    float s = 0.f;
    for (int v = tid; v < CHUNK; v += 256) s += expf(row[v] - gm);
    sv[tid] = s;
    __syncthreads();
    for (int r = 128; r > 0; r >>= 1){
        if (tid < r) sv[tid] += sv[tid+r];
        __syncthreads();
    }
    if (tid == 0) g_ps[b*8+c] = sv[0];
}

__global__ void __launch_bounds__(256) smax3(float* __restrict__ out, int t){
    int c = blockIdx.x, b = blockIdx.y, tid = threadIdx.x;
    float gm = g_pm[b*8];
    #pragma unroll
    for (int i = 1; i < 8; i++) gm = fmaxf(gm, g_pm[b*8+i]);
    float sum = 0.f;
    #pragma unroll
    for (int i = 0; i < 8; i++) sum += g_ps[b*8+i];
    float inv = 1.0f / sum;
    const float* row = g_logits + (size_t)b*V + c*CHUNK;
    float* dst = out + ((size_t)b*TSTEPS + t)*V + c*CHUNK;
    for (int v = tid; v < CHUNK; v += 256) dst[v] = expf(row[v] - gm) * inv;
}

// ================= launch =================
extern "C" void kernel_launch(void* const* d_in, const int* in_sizes, int n_in,
                              void* d_out, int out_size)
{
    int s = (n_in >= 13) ? 1 : ((in_sizes[1] == 1) ? 1 : 0);
    const float* ctx  = (const float*)d_in[0];
    const float* emb  = (const float*)d_in[1+s];
    const float* Wih0 = (const float*)d_in[2+s];
    const float* Whh0 = (const float*)d_in[3+s];
    const float* bih0 = (const float*)d_in[4+s];
    const float* bhh0 = (const float*)d_in[5+s];
    const float* Wih1 = (const float*)d_in[6+s];
    const float* Whh1 = (const float*)d_in[7+s];
    const float* bih1 = (const float*)d_in[8+s];
    const float* bhh1 = (const float*)d_in[9+s];
    const float* Wlin = (const float*)d_in[10+s];
    const float* blin = (const float*)d_in[11+s];
    float* out = (float*)d_out;

    cudaFuncSetAttribute(logits_mma, cudaFuncAttributeMaxDynamicSharedMemorySize, 104448);

    init_kernel<<<128, 256>>>();
    tr_lstm<0><<<dim3(NROWS/32, K2/32), dim3(32,8)>>>(Wih0, Whh0);
    tr_lstm<1><<<dim3(NROWS/32, K2/32), dim3(32,8)>>>(Wih1, Whh1);
    prep_lin<<<V, 256>>>(Wlin);

    for (int t = 0; t < TSTEPS; t++){
        lstm_gemm<0><<<256, 128>>>(emb, ctx);
        lstm_gates<0><<<128, 256>>>(bih0, bhh0);
        lstm_gemm<1><<<256, 128>>>(emb, ctx);
        lstm_gates<1><<<128, 256>>>(bih1, bhh1);
        logits_mma<<<500, 256, 104448>>>(blin);
        smax1<<<dim3(8,B), 256>>>();
        argmax_exact<<<B, 256>>>(Wlin, blin);
        smax2<<<dim3(8,B), 256>>>();
        smax3<<<dim3(8,B), 256>>>(out, t);
    }
}

// round 9
// speedup vs baseline: 2.7761x; 1.1111x over previous
#include <cuda_runtime.h>
#include <cuda_bf16.h>
#include <math.h>

#define B       32
#define HID     1024
#define K2      2048
#define V       32000
#define TSTEPS  64
#define NROWS   4096
#define KSPLIT  8
#define KCHUNK  256
#define START_TOK 1

// ================= persistent device scratch =================
__device__ float g_Wt0[(size_t)K2*NROWS];   // layer0 [Wih|Whh]^T [k][row]  (fp32)
__device__ float g_Wt1[(size_t)K2*NROWS];
__device__ uint4 g_WL[(size_t)V*256];       // W_lin 2-split bf16 interleaved
__device__ uint4 g_XL[32*256];              // h1 2-split bf16
__device__ float g_h0[B*HID], g_c0[B*HID], g_h1[B*HID], g_c1[B*HID];
__device__ float g_part[(size_t)KSPLIT*NROWS*B];
__device__ float g_logits[(size_t)B*V];
__device__ int   g_tok[B];
__device__ float g_pm[B*8], g_ps[B*8];
__device__ float g_cv[B*8];                 // per-chunk exact best value
__device__ int   g_ci[B*8];                 // per-chunk exact best index

// ================= f32x2 helpers (fp32 LSTM path — FROZEN, R7 bitwise) =================
static __device__ __forceinline__ unsigned long long ffma2(unsigned long long a,
                                                           unsigned long long b,
                                                           unsigned long long c){
    unsigned long long d;
    asm("fma.rn.f32x2 %0, %1, %2, %3;" : "=l"(d) : "l"(a), "l"(b), "l"(c));
    return d;
}
static __device__ __forceinline__ unsigned long long pack2(float x, float y){
    unsigned long long d;
    asm("mov.b64 %0, {%1, %2};" : "=l"(d) : "f"(x), "f"(y));
    return d;
}
static __device__ __forceinline__ float2 unpack2(unsigned long long a){
    float2 r;
    asm("mov.b64 {%0, %1}, %2;" : "=f"(r.x), "=f"(r.y) : "l"(a));
    return r;
}
static __device__ __forceinline__ float sigmoidf_(float x){ return 1.0f/(1.0f + expf(-x)); }

// ================= bf16 helpers (logits path) =================
static __device__ __forceinline__ unsigned short f2bf(float x){
    __nv_bfloat16 h = __float2bfloat16(x);
    return *reinterpret_cast<unsigned short*>(&h);
}
static __device__ __forceinline__ float bf2f(unsigned short u){
    __nv_bfloat16 h = *reinterpret_cast<__nv_bfloat16*>(&u);
    return __bfloat162float(h);
}
static __device__ __forceinline__ uint4 pack4(float4 v){
    unsigned short hx=f2bf(v.x), hy=f2bf(v.y), hz=f2bf(v.z), hw=f2bf(v.w);
    unsigned short lx=f2bf(v.x-bf2f(hx)), ly=f2bf(v.y-bf2f(hy));
    unsigned short lz=f2bf(v.z-bf2f(hz)), lw=f2bf(v.w-bf2f(hw));
    uint4 o;
    o.x = (unsigned)hx | ((unsigned)hy<<16);
    o.y = (unsigned)lx | ((unsigned)ly<<16);
    o.z = (unsigned)hz | ((unsigned)hw<<16);
    o.w = (unsigned)lz | ((unsigned)lw<<16);
    return o;
}
static __device__ __forceinline__ void store_hl(unsigned short* rowbase, int k, float v){
    unsigned short hi = f2bf(v);
    unsigned short lo = f2bf(v - bf2f(hi));
    int idx = (k>>2)*8 + ((k>>1)&1)*4 + (k&1);
    rowbase[idx]   = hi;
    rowbase[idx+2] = lo;
}
static __device__ __forceinline__ void cpa16(void* dst, const void* src){
    unsigned ds = (unsigned)__cvta_generic_to_shared(dst);
    asm volatile("cp.async.cg.shared.global [%0], [%1], 16;\n" :: "r"(ds), "l"(src));
}
#define CP_COMMIT asm volatile("cp.async.commit_group;\n")
#define CP_WAIT(n) asm volatile("cp.async.wait_group %0;\n" :: "n"(n))
static __device__ __forceinline__ uint2 ld2(const char* base, int row, int pair){
    return *(const uint2*)(base + row*544 + pair*8);
}
static __device__ __forceinline__ void mma16816(float* d,
    unsigned a0, unsigned a1, unsigned a2, unsigned a3, unsigned b0, unsigned b1){
    asm volatile("mma.sync.aligned.m16n8k16.row.col.f32.bf16.bf16.f32 "
        "{%0,%1,%2,%3},{%4,%5,%6,%7},{%8,%9},{%0,%1,%2,%3};"
        : "+f"(d[0]), "+f"(d[1]), "+f"(d[2]), "+f"(d[3])
        : "r"(a0), "r"(a1), "r"(a2), "r"(a3), "r"(b0), "r"(b1));
}

// ================= init =================
__global__ void init_kernel(){
    int i = blockIdx.x*blockDim.x + threadIdx.x;
    if (i < B*HID){ g_h0[i]=0.f; g_c0[i]=0.f; g_h1[i]=0.f; g_c1[i]=0.f; }
    if (i < 8192) ((uint4*)g_XL)[i] = make_uint4(0,0,0,0);
    if (i < B) g_tok[i] = START_TOK;
}

// ================= prep =================
template<int L>
__global__ void tr_lstm(const float* __restrict__ Wih, const float* __restrict__ Whh){
    __shared__ float t[32][33];
    int rb = blockIdx.x*32, kb = blockIdx.y*32;
    int x = threadIdx.x, y = threadIdx.y;
    const float* src = (kb < 1024) ? Wih : Whh;
    int ko = (kb < 1024) ? kb : kb - 1024;
    #pragma unroll
    for (int j = 0; j < 32; j += 8) t[y+j][x] = src[(size_t)(rb+y+j)*1024 + ko + x];
    __syncthreads();
    float* dst = L ? g_Wt1 : g_Wt0;
    #pragma unroll
    for (int j = 0; j < 32; j += 8) dst[(size_t)(kb+y+j)*NROWS + rb + x] = t[x][y+j];
}
__global__ void prep_lin(const float* __restrict__ W){
    int v = blockIdx.x, j = threadIdx.x;
    float4 x = *(const float4*)(W + (size_t)v*1024 + j*4);
    g_WL[(size_t)v*256 + j] = pack4(x);
}

// ================= LSTM GEMM partials (FROZEN, R7 bitwise) =================
template<int L>
__global__ void __launch_bounds__(128) lstm_gemm(const float* __restrict__ emb,
                                                 const float* __restrict__ ctx)
{
    __shared__ __align__(16) float Xs[KCHUNK][32];
    const int tid   = threadIdx.x;
    const int split = blockIdx.x & 7;
    const int row   = (blockIdx.x >> 3)*128 + tid;
    const int kbase = split*KCHUNK;
    const float* __restrict__ Wt = L ? g_Wt1 : g_Wt0;

    {
        int b = tid >> 2, q = tid & 3;
        const float* src;
        if (L == 0){
            if (split < 2)      src = emb + (size_t)g_tok[b]*512 + kbase;
            else if (split < 4) src = ctx + (size_t)b*512 + (kbase - 512);
            else                src = g_h0 + b*HID + (kbase - 1024);
        } else {
            if (split < 4)      src = g_h0 + b*HID + kbase;
            else                src = g_h1 + b*HID + (kbase - 1024);
        }
        #pragma unroll
        for (int i = 0; i < 16; i++){
            int kf = (q + i*4)*4;
            float4 v = *(const float4*)(src + kf);
            Xs[kf+0][b]=v.x; Xs[kf+1][b]=v.y; Xs[kf+2][b]=v.z; Xs[kf+3][b]=v.w;
        }
    }
    __syncthreads();

    unsigned long long acc[16];
    #pragma unroll
    for (int i = 0; i < 16; i++) acc[i] = 0ull;

    const float* __restrict__ wp = Wt + (size_t)kbase*NROWS + row;
    float wA[16], wB[16];
    #pragma unroll
    for (int i = 0; i < 16; i++) wA[i] = wp[(size_t)i*NROWS];

    #pragma unroll 1
    for (int kb = 0; kb < KCHUNK; kb += 32){
        #pragma unroll
        for (int i = 0; i < 16; i++) wB[i] = wp[(size_t)(kb+16+i)*NROWS];
        #pragma unroll
        for (int i = 0; i < 16; i++){
            unsigned long long ww = pack2(wA[i], wA[i]);
            const ulonglong2* xr = (const ulonglong2*)Xs[kb+i];
            #pragma unroll
            for (int j = 0; j < 8; j++){
                ulonglong2 x2 = xr[j];
                acc[2*j]   = ffma2(ww, x2.x, acc[2*j]);
                acc[2*j+1] = ffma2(ww, x2.y, acc[2*j+1]);
            }
        }
        if (kb + 32 < KCHUNK){
            #pragma unroll
            for (int i = 0; i < 16; i++) wA[i] = wp[(size_t)(kb+32+i)*NROWS];
        }
        #pragma unroll
        for (int i = 0; i < 16; i++){
            unsigned long long ww = pack2(wB[i], wB[i]);
            const ulonglong2* xr = (const ulonglong2*)Xs[kb+16+i];
            #pragma unroll
            for (int j = 0; j < 8; j++){
                ulonglong2 x2 = xr[j];
                acc[2*j]   = ffma2(ww, x2.x, acc[2*j]);
                acc[2*j+1] = ffma2(ww, x2.y, acc[2*j+1]);
            }
        }
    }

    float* pp = g_part + ((size_t)split*NROWS + row)*32;
    #pragma unroll
    for (int j = 0; j < 8; j++){
        float2 a = unpack2(acc[2*j]);
        float2 c = unpack2(acc[2*j+1]);
        *(float4*)(pp + j*4) = make_float4(a.x, a.y, c.x, c.y);
    }
}

// ================= gates (FROZEN, R7 bitwise) =================
template<int L>
__global__ void __launch_bounds__(256) lstm_gates(const float* __restrict__ bih,
                                                  const float* __restrict__ bhh)
{
    int idx = blockIdx.x*256 + threadIdx.x;
    int b = idx & 31, u = idx >> 5;
    float g[4];
    #pragma unroll
    for (int gg = 0; gg < 4; gg++){
        int r = gg*HID + u;
        float s = bih[r] + bhh[r];
        #pragma unroll
        for (int sp = 0; sp < KSPLIT; sp++)
            s += g_part[((size_t)sp*NROWS + r)*32 + b];
        g[gg] = s;
    }
    float iv = sigmoidf_(g[0]), fv = sigmoidf_(g[1]), ov = sigmoidf_(g[3]);
    float tv = tanhf(g[2]);
    float* cp = L ? g_c1 : g_c0;
    float* hp = L ? g_h1 : g_h0;
    int id = b*HID + u;
    float cn = fv*cp[id] + iv*tv;
    cp[id] = cn;
    float h = ov*tanhf(cn);
    hp[id] = h;
    if (L == 1) store_hl((unsigned short*)g_XL + b*2048, u, h);
}

// ================= logits: 3-term 2-split bf16 MMA (unchanged, R7) =================
__global__ void __launch_bounds__(256) logits_mma(const float* __restrict__ blin)
{
    extern __shared__ __align__(16) char sm[];
    const int tid = threadIdx.x, lane = tid & 31, w = tid >> 5;
    const int mi = w & 3, ki = w >> 2;
    const uint4* __restrict__ Wsrc = g_WL + (size_t)blockIdx.x*64*256;
    const uint4* __restrict__ Xsrc = g_XL;

    float d[4][4];
    #pragma unroll
    for (int i = 0; i < 4; i++){ d[i][0]=0.f; d[i][1]=0.f; d[i][2]=0.f; d[i][3]=0.f; }

    {
        char* smw = sm; char* smx = sm + 34816;
        #pragma unroll
        for (int j = 0; j < 8; j++){
            int s = tid + j*256, row = s >> 5, c = s & 31;
            cpa16(smw + row*544 + c*16, Wsrc + (size_t)row*256 + c);
        }
        #pragma unroll
        for (int j = 0; j < 4; j++){
            int s = tid + j*256, row = s >> 5, c = s & 31;
            cpa16(smx + row*544 + c*16, Xsrc + (size_t)row*256 + c);
        }
        CP_COMMIT;
    }

    for (int ck = 0; ck < 8; ck++){
        if (ck < 7){
            char* smw = sm + ((ck+1)&1)*52224; char* smx = smw + 34816;
            #pragma unroll
            for (int j = 0; j < 8; j++){
                int s = tid + j*256, row = s >> 5, c = s & 31;
                cpa16(smw + row*544 + c*16, Wsrc + (size_t)row*256 + (ck+1)*32 + c);
            }
            #pragma unroll
            for (int j = 0; j < 4; j++){
                int s = tid + j*256, row = s >> 5, c = s & 31;
                cpa16(smx + row*544 + c*16, Xsrc + (size_t)row*256 + (ck+1)*32 + c);
            }
            CP_COMMIT;
            CP_WAIT(1);
        } else {
            CP_WAIT(0);
        }
        __syncthreads();
        const char* smw = sm + (ck&1)*52224;
        const char* smx = smw + 34816;
        const int r0 = mi*16 + (lane>>2);
        #pragma unroll
        for (int s = 0; s < 4; s++){
            int ap = (ki*4 + s)*8 + (lane&3);
            uint2 A0 = ld2(smw, r0,   ap);
            uint2 A1 = ld2(smw, r0+8, ap);
            uint2 A2 = ld2(smw, r0,   ap+4);
            uint2 A3 = ld2(smw, r0+8, ap+4);
            #pragma unroll
            for (int nt = 0; nt < 4; nt++){
                int n = nt*8 + (lane>>2);
                uint2 B0 = ld2(smx, n, ap);
                uint2 B1 = ld2(smx, n, ap+4);
                mma16816(d[nt], A0.x,A1.x,A2.x,A3.x, B0.x,B1.x);
                mma16816(d[nt], A0.x,A1.x,A2.x,A3.x, B0.y,B1.y);
                mma16816(d[nt], A0.y,A1.y,A2.y,A3.y, B0.x,B1.x);
            }
        }
        __syncthreads();
    }

    float* Gs = (float*)sm;
    {
        int r = mi*16 + (lane>>2), cb = (lane&3)*2;
        #pragma unroll
        for (int nt = 0; nt < 4; nt++){
            int n = nt*8 + cb;
            Gs[(ki*64 + r  )*33 + n  ] = d[nt][0];
            Gs[(ki*64 + r  )*33 + n+1] = d[nt][1];
            Gs[(ki*64 + r+8)*33 + n  ] = d[nt][2];
            Gs[(ki*64 + r+8)*33 + n+1] = d[nt][3];
        }
    }
    __syncthreads();
    #pragma unroll
    for (int j = 0; j < 8; j++){
        int idx = tid + j*256;
        int b = idx >> 6, r = idx & 63;
        int v = blockIdx.x*64 + r;
        g_logits[(size_t)b*V + v] = Gs[r*33 + b] + Gs[(64 + r)*33 + b] + blin[v];
    }
}

// ================= fused: online softmax (max+sum) + per-chunk exact argmax candidates =================
#define CHUNK (V/8)   // 4000

__global__ void __launch_bounds__(256) smax12c(const float* __restrict__ Wlin,
                                               const float* __restrict__ blin){
    __shared__ float sm[256], ss[256];
    __shared__ int   cand[32];
    __shared__ float cval[32];
    __shared__ int   ncand;
    int c = blockIdx.x, b = blockIdx.y, tid = threadIdx.x;
    if (tid == 0) ncand = 0;
    const float* row = g_logits + (size_t)b*V + c*CHUNK;

    float m = -INFINITY, s = 0.f;
    for (int v = tid; v < CHUNK; v += 256){
        float x = row[v];
        if (x > m){ s *= expf(m - x); m = x; }
        s += expf(x - m);
    }
    sm[tid] = m; ss[tid] = s;
    __syncthreads();
    for (int st = 128; st > 0; st >>= 1){
        if (tid < st){
            float m2 = sm[tid+st], s2 = ss[tid+st];
            float M = fmaxf(sm[tid], m2);
            ss[tid] = ss[tid]*expf(sm[tid]-M) + s2*expf(m2-M);
            sm[tid] = M;
        }
        __syncthreads();
    }
    const float lmax = sm[0];
    if (tid == 0){ g_pm[b*8+c] = lmax; g_ps[b*8+c] = ss[0]; }

    // ---- collect candidates (>= lmax - eps); superset of global near-max set ----
    const float thr = lmax - 1e-3f;
    for (int v = tid; v < CHUNK; v += 256){
        if (row[v] >= thr){
            int sl = atomicAdd(&ncand, 1);
            if (sl < 32) cand[sl] = v + c*CHUNK;
        }
    }
    __syncthreads();
    int nc = min(ncand, 32);
    // ---- exact fp32 recompute (warp per candidate) ----
    int w = tid >> 5, lane = tid & 31;
    const float* h = g_h1 + b*HID;
    for (int ci = w; ci < nc; ci += 8){
        int v = cand[ci];
        const float* wr = Wlin + (size_t)v*1024;
        float acc = 0.f;
        #pragma unroll 8
        for (int k = lane; k < 1024; k += 32) acc += h[k]*wr[k];
        #pragma unroll
        for (int o = 16; o > 0; o >>= 1) acc += __shfl_xor_sync(0xffffffffu, acc, o);
        if (lane == 0) cval[ci] = acc + blin[v];
    }
    __syncthreads();
    if (tid == 0){
        float bm = -INFINITY; int bi = 1<<30;
        for (int i = 0; i < nc; i++){
            if (cval[i] > bm || (cval[i] == bm && cand[i] < bi)){ bm = cval[i]; bi = cand[i]; }
        }
        g_cv[b*8+c] = bm; g_ci[b*8+c] = bi;
    }
}

// ================= normalize + write probs + combine argmax -> g_tok =================
__global__ void __launch_bounds__(256) smax3(float* __restrict__ out, int t){
    int c = blockIdx.x, b = blockIdx.y, tid = threadIdx.x;
    if (c == 0 && tid == 0){
        float bm = -INFINITY; int bi = 1<<30;
        #pragma unroll
        for (int i = 0; i < 8; i++){
            float v = g_cv[b*8+i]; int ix = g_ci[b*8+i];
            if (v > bm || (v == bm && ix < bi)){ bm = v; bi = ix; }
        }
        g_tok[b] = bi;
    }
    float gm = g_pm[b*8];
    #pragma unroll
    for (int i = 1; i < 8; i++) gm = fmaxf(gm, g_pm[b*8+i]);
    float sum = 0.f;
    #pragma unroll
    for (int i = 0; i < 8; i++) sum += g_ps[b*8+i]*expf(g_pm[b*8+i] - gm);
    float inv = 1.0f / sum;
    const float* row = g_logits + (size_t)b*V + c*CHUNK;
    float* dst = out + ((size_t)b*TSTEPS + t)*V + c*CHUNK;
    for (int v = tid; v < CHUNK; v += 256) dst[v] = expf(row[v] - gm) * inv;
}

// ================= launch =================
extern "C" void kernel_launch(void* const* d_in, const int* in_sizes, int n_in,
                              void* d_out, int out_size)
{
    int s = (n_in >= 13) ? 1 : ((in_sizes[1] == 1) ? 1 : 0);
    const float* ctx  = (const float*)d_in[0];
    const float* emb  = (const float*)d_in[1+s];
    const float* Wih0 = (const float*)d_in[2+s];
    const float* Whh0 = (const float*)d_in[3+s];
    const float* bih0 = (const float*)d_in[4+s];
    const float* bhh0 = (const float*)d_in[5+s];
    const float* Wih1 = (const float*)d_in[6+s];
    const float* Whh1 = (const float*)d_in[7+s];
    const float* bih1 = (const float*)d_in[8+s];
    const float* bhh1 = (const float*)d_in[9+s];
    const float* Wlin = (const float*)d_in[10+s];
    const float* blin = (const float*)d_in[11+s];
    float* out = (float*)d_out;

    cudaFuncSetAttribute(logits_mma, cudaFuncAttributeMaxDynamicSharedMemorySize, 104448);

    init_kernel<<<128, 256>>>();
    tr_lstm<0><<<dim3(NROWS/32, K2/32), dim3(32,8)>>>(Wih0, Whh0);
    tr_lstm<1><<<dim3(NROWS/32, K2/32), dim3(32,8)>>>(Wih1, Whh1);
    prep_lin<<<V, 256>>>(Wlin);

    for (int t = 0; t < TSTEPS; t++){
        lstm_gemm<0><<<256, 128>>>(emb, ctx);
        lstm_gates<0><<<128, 256>>>(bih0, bhh0);
        lstm_gemm<1><<<256, 128>>>(emb, ctx);
        lstm_gates<1><<<128, 256>>>(bih1, bhh1);
        logits_mma<<<500, 256, 104448>>>(blin);
        smax12c<<<dim3(8,B), 256>>>(Wlin, blin);
        smax3<<<dim3(8,B), 256>>>(out, t);
    }
}